// round 14
// baseline (speedup 1.0000x reference)
#include <cuda_runtime.h>

#define BN 4096
#define DD 2048
#define MARGINF 0.05f
#define HDELTA 0.1f
#define NPBLK 1118          // live lower-triangle tiles
#define NSIM  512           // k_sim blocks (8 rows each); all co-resident

// persistent scratch (no allocation allowed in kernel_launch)
__device__ float2 g_so[BN];        // {sim, overall} per SORTED position
__device__ int    g_hist[4096];    // bucket histogram (zeroed by scan block)
__device__ int    g_off[4096];     // exclusive bucket offsets (scatter cursor)
__device__ float  g_hub[BN];       // per-row huber partial (4 terms)
__device__ float  g_psum[NPBLK];   // per-block pair-loss partial
__device__ int    g_pcnt[NPBLK];   // per-block mask count partial
__device__ int    g_ticket;        // k_pairs final ticket (reset by its last block)
__device__ int    g_t2;            // k_sim hist ticket (reset by scan block)
__device__ volatile int g_ready;   // scan-done flag (reset by k_pairs last block)

__device__ __forceinline__ int bucketf(float o) {
    int b = (int)(o * 4096.0f);
    return b < 0 ? 0 : (b > 4095 ? 4095 : b);
}

// ---------------------------------------------------------------------------
// Kernel 1: fused {histogram -> (last block) scan} + warp-per-row cosine sim
// + huber + sorted scatter.  No grid barrier: a one-way g_ready flag, set by
// the scan (which runs ~1.5us into a ~7us HBM phase), checked only at the
// scatter.  All 512 blocks are co-resident (<=40 regs), so the flag-setter
// is always scheduled -> no deadlock.  All counters return to 0 each run.
// ---------------------------------------------------------------------------
__global__ void __launch_bounds__(256) k_sim(
    const float* __restrict__ zr, const float* __restrict__ zp,
    const float* __restrict__ pred, const float* __restrict__ tgt) {
    __shared__ int ws[8];
    __shared__ int s_scan;
    int t    = threadIdx.x;
    int lane = t & 31;
    int warp = t >> 5;
    int blk  = blockIdx.x;
    int row  = blk * 8 + warp;

    // ---- histogram prologue: this block's 8 rows ----
    if (t < 8) atomicAdd(&g_hist[bucketf(tgt[(blk * 8 + t) * 5 + 4])], 1);
    __syncthreads();
    if (t == 0) {
        __threadfence();
        int old = atomicAdd(&g_t2, 1);
        s_scan = (old == NSIM - 1);
    }
    __syncthreads();

    if (s_scan) {
        // ---- last block: exclusive scan g_hist[4096] -> g_off ----
        __threadfence();                       // acquire all hist atomics
        int base = t * 16;
        int h[16];
        int tot = 0;
#pragma unroll
        for (int k = 0; k < 16; k++) { h[k] = g_hist[base + k]; tot += h[k]; }
        int sc = tot;
#pragma unroll
        for (int o = 1; o < 32; o <<= 1) {
            int v = __shfl_up_sync(0xffffffffu, sc, o);
            if (lane >= o) sc += v;
        }
        if (lane == 31) ws[warp] = sc;
        __syncthreads();
        if (warp == 0) {
            int v = (lane < 8) ? ws[lane] : 0;
            int s2 = v;
#pragma unroll
            for (int o = 1; o < 8; o <<= 1) {
                int u = __shfl_up_sync(0xffffffffu, s2, o);
                if (lane >= o) s2 += u;
            }
            if (lane < 8) ws[lane] = s2 - v;   // exclusive warp bases
        }
        __syncthreads();
        int run = (sc - tot) + ws[warp];
#pragma unroll
        for (int k = 0; k < 16; k++) {
            g_off[base + k] = run;
            run += h[k];
            g_hist[base + k] = 0;              // restore for next replay
        }
        __syncthreads();
        if (t == 0) {
            g_t2 = 0;                          // restore for next replay
            __threadfence();
            g_ready = 1;                       // release: offsets are live
        }
    }

    // ---- cosine sim (HBM-bound; hides the scan) ----
    const float4* a = reinterpret_cast<const float4*>(zr) + (size_t)row * (DD / 4) + lane;
    const float4* b = reinterpret_cast<const float4*>(zp) + (size_t)row * (DD / 4) + lane;

    float d0 = 0.f, d1 = 0.f, na0 = 0.f, na1 = 0.f, nb0 = 0.f, nb1 = 0.f;
#pragma unroll
    for (int k = 0; k < 16; k += 2) {
        float4 x0 = a[k * 32];
        float4 y0 = b[k * 32];
        float4 x1 = a[(k + 1) * 32];
        float4 y1 = b[(k + 1) * 32];
        d0  += x0.x * y0.x + x0.y * y0.y + x0.z * y0.z + x0.w * y0.w;
        na0 += x0.x * x0.x + x0.y * x0.y + x0.z * x0.z + x0.w * x0.w;
        nb0 += y0.x * y0.x + y0.y * y0.y + y0.z * y0.z + y0.w * y0.w;
        d1  += x1.x * y1.x + x1.y * y1.y + x1.z * y1.z + x1.w * y1.w;
        na1 += x1.x * x1.x + x1.y * x1.y + x1.z * x1.z + x1.w * x1.w;
        nb1 += y1.x * y1.x + y1.y * y1.y + y1.z * y1.z + y1.w * y1.w;
    }
    float dot = d0 + d1, na = na0 + na1, nb = nb0 + nb1;
#pragma unroll
    for (int o = 16; o > 0; o >>= 1) {
        dot += __shfl_xor_sync(0xffffffffu, dot, o);
        na  += __shfl_xor_sync(0xffffffffu, na,  o);
        nb  += __shfl_xor_sync(0xffffffffu, nb,  o);
    }
    if (lane == 0) {
        float sim = dot / (fmaxf(sqrtf(na), 1e-8f) * fmaxf(sqrtf(nb), 1e-8f));
        float ov  = tgt[row * 5 + 4];
        float h = 0.f;
#pragma unroll
        for (int k = 0; k < 4; k++) {
            float d = pred[row * 4 + k] - tgt[row * 5 + k];
            float ad = fabsf(d);
            h += (ad <= HDELTA) ? (0.5f * d * d) : (HDELTA * (ad - 0.5f * HDELTA));
        }
        g_hub[row] = h;
        while (g_ready == 0) { }               // near-zero wait in practice
        __threadfence();                       // acquire g_off
        int pos = atomicAdd(&g_off[bucketf(ov)], 1);
        g_so[pos] = make_float2(sim, ov);
    }
}

// ---------------------------------------------------------------------------
// Kernel 2: triangular masked margin reduction over sorted g_so + fused final.
// Tiles: i-chunk 256 (1 row/thread) x j-tile 32; live tiles per i-chunk ci:
// min(128, 8*ci+10); prefix T(ci) = 4*ci^2 + 6*ci, inverted in closed form.
// Classification per thread:
//   b_i > b_jhi -> mask all-true (3 instr/pair, count free)
//   b_i < b_jlo -> all-false (skip)
//   else        -> exact o-compare (thin diagonal band; handles ties)
// relu identity: relu(s_j - s_i + m) = (s_j > t_i)*(s_j - t_i), t_i = s_i - m.
// Last block (ticket) reduces partials + huber -> out[0..2] and resets
// g_ticket / g_ready for the next replay.
// ---------------------------------------------------------------------------
__global__ void __launch_bounds__(256) k_pairs(float* __restrict__ out) {
    __shared__ float sjx[32], sjy[32];
    __shared__ float wa[8], wh[8];
    __shared__ int   wc[8];
    __shared__ int   s_last;

    int t = threadIdx.x;
    // closed-form tile decode
    int bid = blockIdx.x;
    float f = sqrtf(16.f * (float)bid + 36.f);
    int ci = (int)((f - 6.f) * 0.125f);
    if (ci > 15) ci = 15;
    if (ci < 15 && (4 * (ci + 1) * (ci + 1) + 6 * (ci + 1)) <= bid) ci++;
    int base = 4 * ci * ci + 6 * ci;
    if (base > bid) { ci--; base = 4 * ci * ci + 6 * ci; }
    int jb = (bid - base) * 32, ib = ci * 256;

    float2 vi = g_so[ib + t];              // early load (latency overlap)
    if (t < 32) { float2 s = g_so[jb + t]; sjx[t] = s.x; sjy[t] = s.y; }
    __syncthreads();

    float ti = vi.x - MARGINF;
    float oi = vi.y;
    int b_i   = bucketf(oi);
    int b_jlo = bucketf(sjy[0]);
    int b_jhi = bucketf(sjy[31]);

    float a = 0.f;
    int   c = 0, kk = 0;
    if (b_i > b_jhi) {
        float a0 = 0.f, a1 = 0.f; int k0 = 0, k1 = 0;
#pragma unroll
        for (int j = 0; j < 32; j += 2) {
            float s0 = sjx[j], s1 = sjx[j + 1];
            if (s0 > ti) { a0 += s0; k0++; }
            if (s1 > ti) { a1 += s1; k1++; }
        }
        a = a0 + a1; kk = k0 + k1; c = 32;
    } else if (b_i >= b_jlo) {
        float a0 = 0.f, a1 = 0.f; int k0 = 0, k1 = 0, c0 = 0, c1 = 0;
#pragma unroll
        for (int j = 0; j < 32; j += 2) {
            float s0 = sjx[j], y0 = sjy[j];
            float s1 = sjx[j + 1], y1 = sjy[j + 1];
            bool m0 = oi > y0, m1 = oi > y1;
            if (m0) c0++;
            if (m0 && s0 > ti) { a0 += s0; k0++; }
            if (m1) c1++;
            if (m1 && s1 > ti) { a1 += s1; k1++; }
        }
        a = a0 + a1; kk = k0 + k1; c = c0 + c1;
    }
    a -= ti * (float)kk;

    c = __reduce_add_sync(0xffffffffu, c);
#pragma unroll
    for (int o = 16; o > 0; o >>= 1)
        a += __shfl_xor_sync(0xffffffffu, a, o);

    if ((t & 31) == 0) { wa[t >> 5] = a; wc[t >> 5] = c; }
    __syncthreads();
    if (t == 0) {
        a = 0.f; c = 0;
#pragma unroll
        for (int k = 0; k < 8; k++) { a += wa[k]; c += wc[k]; }
        g_psum[blockIdx.x] = a;
        g_pcnt[blockIdx.x] = c;
        __threadfence();
        int old = atomicAdd(&g_ticket, 1);
        s_last = (old == NPBLK - 1);
        if (s_last) { g_ticket = 0; g_ready = 0; }   // restore for next replay
    }
    __syncthreads();

    // ---- last block: final reduction (fixed-order -> deterministic) ----
    if (s_last) {
        float pa = 0.f;
        int   pc = 0;
        float h  = 0.f;
#pragma unroll
        for (int k = 0; k < 5; k++) {
            int idx = t + k * 256;
            if (idx < NPBLK) { pa += g_psum[idx]; pc += g_pcnt[idx]; }
        }
#pragma unroll
        for (int k = 0; k < 16; k++) h += g_hub[t + k * 256];
        pc = __reduce_add_sync(0xffffffffu, pc);
#pragma unroll
        for (int o = 16; o > 0; o >>= 1) {
            pa += __shfl_xor_sync(0xffffffffu, pa, o);
            h  += __shfl_xor_sync(0xffffffffu, h,  o);
        }
        if ((t & 31) == 0) { wa[t >> 5] = pa; wc[t >> 5] = pc; wh[t >> 5] = h; }
        __syncthreads();
        if (t == 0) {
            pa = 0.f; pc = 0; h = 0.f;
#pragma unroll
            for (int k = 0; k < 8; k++) { pa += wa[k]; pc += wc[k]; h += wh[k]; }
            float Lc = (pc > 0) ? (pa / fmaxf((float)pc, 1.f)) : 0.f;
            float Ls = h / (float)(BN * 4);
            out[0] = Lc + Ls;   // lambda_c = lambda_s = 1
            out[1] = Lc;
            out[2] = Ls;
        }
    }
}

extern "C" void kernel_launch(void* const* d_in, const int* in_sizes, int n_in,
                              void* d_out, int out_size) {
    const float* zr   = (const float*)d_in[0];
    const float* zp   = (const float*)d_in[1];
    const float* pred = (const float*)d_in[2];
    const float* tgt  = (const float*)d_in[3];

    k_sim<<<NSIM, 256>>>(zr, zp, pred, tgt);
    k_pairs<<<NPBLK, 256>>>((float*)d_out);
}